// round 5
// baseline (speedup 1.0000x reference)
#include <cuda_runtime.h>
#include <cuda_fp16.h>
#include <math.h>
#include <stdint.h>

// Problem constants
#define Bsz 2
#define Sq  1024
#define Dm  1024
#define Hn  16
#define Dhd 64
#define Mrows (Bsz*Sq)                       // 2048
#define OUT_ELEMS  ((size_t)Bsz*Sq*Dm)
#define ATTN_ELEMS ((size_t)Bsz*Hn*Sq*Sq)

typedef __half  f16;
typedef __half2 f162;

// ---------------------------------------------------------------------------
// Scratch (device globals; allocation-free)
// ---------------------------------------------------------------------------
__device__ __align__(16) float g_V  [Mrows*Dm];
__device__ __align__(16) float g_x1 [Mrows*Dm];
__device__ __align__(16) float g_ff [Mrows*Dm];
__device__ __align__(16) float g_attn_fb[ATTN_ELEMS];

__device__ __align__(16) f16 g_xh [Mrows*Dm], g_xl [Mrows*Dm];
__device__ __align__(16) f16 g_Qh [Mrows*Dm], g_Ql [Mrows*Dm];
__device__ __align__(16) f16 g_Kh [Mrows*Dm], g_Kl [Mrows*Dm];
__device__ __align__(16) f16 g_avh[Mrows*Dm];
__device__ __align__(16) f16 g_x1h[Mrows*Dm];
__device__ __align__(16) f16 g_h1h[Mrows*Dm];
__device__ __align__(16) f16 g_Wh [6*Dm*Dm], g_Wl [6*Dm*Dm];
__device__ __align__(16) f16 g_Vth[32*64*1024], g_Vtl[32*64*1024];
__device__ __align__(16) f16 g_Ph [ATTN_ELEMS];

// ---------------------------------------------------------------------------
// PTX helpers (sm_80-baseline: mma.sync + ldmatrix + cp.async)
// ---------------------------------------------------------------------------
__device__ __forceinline__ uint32_t smem_u32(const void* p) {
    uint32_t a;
    asm("{ .reg .u64 t; cvta.to.shared.u64 t, %1; cvt.u32.u64 %0, t; }"
        : "=r"(a) : "l"(p));
    return a;
}

__device__ __forceinline__ void ldmx4(uint32_t* r, uint32_t addr) {
    asm volatile("ldmatrix.sync.aligned.m8n8.x4.shared.b16 {%0,%1,%2,%3}, [%4];"
                 : "=r"(r[0]), "=r"(r[1]), "=r"(r[2]), "=r"(r[3]) : "r"(addr));
}

__device__ __forceinline__ void mma16816(float* d, const uint32_t* a, const uint32_t* b) {
    asm volatile(
        "mma.sync.aligned.m16n8k16.row.col.f32.f16.f16.f32 "
        "{%0,%1,%2,%3}, {%4,%5,%6,%7}, {%8,%9}, {%0,%1,%2,%3};"
        : "+f"(d[0]), "+f"(d[1]), "+f"(d[2]), "+f"(d[3])
        : "r"(a[0]), "r"(a[1]), "r"(a[2]), "r"(a[3]), "r"(b[0]), "r"(b[1]));
}

#define CPA16(dst, src)  asm volatile("cp.async.cg.shared.global [%0], [%1], 16;" :: "r"(dst), "l"(src))
#define CPA_COMMIT()     asm volatile("cp.async.commit_group;" ::: "memory")
#define CPA_WAIT2()      asm volatile("cp.async.wait_group 2;" ::: "memory")

__device__ __forceinline__ void split1h(float x, f16& h, f16& l) {
    h = __float2half_rn(x);
    l = __float2half_rn(x - __half2float(h));
}

// ---------------------------------------------------------------------------
// fp32 -> fp16 (hi, lo) split
// ---------------------------------------------------------------------------
__global__ void __launch_bounds__(256) split_kernel(
    const float* __restrict__ src, f16* __restrict__ hi, f16* __restrict__ lo, int n4)
{
    int i = blockIdx.x * 256 + threadIdx.x;
    if (i >= n4) return;
    float4 v = reinterpret_cast<const float4*>(src)[i];
    f16 h0,h1,h2,h3,l0,l1,l2,l3;
    split1h(v.x,h0,l0); split1h(v.y,h1,l1); split1h(v.z,h2,l2); split1h(v.w,h3,l3);
    f162* H = reinterpret_cast<f162*>(hi);
    f162* L = reinterpret_cast<f162*>(lo);
    H[2*i]   = __halves2half2(h0,h1); H[2*i+1] = __halves2half2(h2,h3);
    L[2*i]   = __halves2half2(l0,l1); L[2*i+1] = __halves2half2(l2,l3);
}

// ---------------------------------------------------------------------------
// V transpose + split: V[b,k,h,d] (fp32) -> Vt[bh][d][k] (fp16 hi/lo)
// ---------------------------------------------------------------------------
__global__ void __launch_bounds__(256) vtrans_kernel(
    const float* __restrict__ V, f16* __restrict__ Vth, f16* __restrict__ Vtl)
{
    __shared__ float t[64][129];
    const int tid = threadIdx.x;
    const int bh = blockIdx.y, b = bh >> 4, h = bh & 15;
    const int k0 = blockIdx.x * 128;
#pragma unroll
    for (int i = 0; i < 32; i++) {
        int idx = tid + i * 256;
        int d = idx & 63, kl = idx >> 6;
        t[d][kl] = V[(size_t)(b * Sq + k0 + kl) * Dm + h * Dhd + d];
    }
    __syncthreads();
#pragma unroll
    for (int i = 0; i < 32; i++) {
        int idx = tid + i * 256;
        int kl = idx & 127, d = idx >> 7;
        f16 hh, ll; split1h(t[d][kl], hh, ll);
        size_t o = ((size_t)bh * 64 + d) * Sq + k0 + kl;
        Vth[o] = hh; Vtl[o] = ll;
    }
}

// ---------------------------------------------------------------------------
// Dense NT GEMM (mma.sync fp16). NA=2: 3 products. NA=1: 2 products.
// Block 128x128, 8 warps, warp tile 32x64, K-stage 32, 3-stage cp.async pipe.
// ---------------------------------------------------------------------------
#define DPAD 80
#define DMAT 10240

template<int NA>
__global__ void __launch_bounds__(256, 1) gemm_mma(
    const f16* __restrict__ Ah, const f16* __restrict__ Al,
    const f16* __restrict__ Bh, const f16* __restrict__ Bl,
    const float* __restrict__ bias, int relu,
    float* __restrict__ Cf, f16* __restrict__ Ch, f16* __restrict__ Cl,
    int M, int N, int K)
{
    constexpr int NMAT = NA + 2;
    constexpr int STAGE = NMAT * DMAT;
    extern __shared__ __align__(16) char dsm[];
    const uint32_t s0 = smem_u32(dsm);
    const int tid = threadIdx.x, lane = tid & 31, warp = tid >> 5;
    const int wm = warp & 3, wn = warp >> 2;
    const int m0 = blockIdx.y * 128, n0 = blockIdx.x * 128;

    float acc[2][8][4];
#pragma unroll
    for (int a = 0; a < 2; a++)
#pragma unroll
        for (int b = 0; b < 8; b++)
#pragma unroll
            for (int c = 0; c < 4; c++) acc[a][b][c] = 0.f;

    const f16* srcs[NMAT];
    srcs[0] = Ah + (size_t)m0 * K;
    if (NA == 2) srcs[1] = Al + (size_t)m0 * K;
    srcs[NA]     = Bh + (size_t)n0 * K;
    srcs[NA + 1] = Bl + (size_t)n0 * K;

    auto load_stage = [&](int s, int k0) {
        uint32_t base = s0 + s * STAGE;
        int row0 = tid >> 2, ch = tid & 3;
#pragma unroll
        for (int m = 0; m < NMAT; m++) {
#pragma unroll
            for (int i = 0; i < 2; i++) {
                int row = row0 + i * 64;
                CPA16(base + m * DMAT + row * DPAD + ch * 16,
                      srcs[m] + (size_t)row * K + k0 + ch * 8);
            }
        }
        CPA_COMMIT();
    };

    const int NS = K / 32;
    load_stage(0, 0);
    load_stage(1, 32);
    for (int s = 0; s < NS; s++) {
        if (s + 2 < NS) load_stage((s + 2) % 3, (s + 2) * 32);
        else            CPA_COMMIT();
        CPA_WAIT2();
        __syncthreads();
        uint32_t base = s0 + (s % 3) * STAGE;
#pragma unroll
        for (int ks = 0; ks < 2; ks++) {
            uint32_t a_hi[2][4], a_lo[2][4], b_hi[8][2], b_lo[8][2];
#pragma unroll
            for (int mt = 0; mt < 2; mt++) {
                uint32_t off = (uint32_t)((wm*32 + mt*16 + (lane & 15)) * DPAD
                                          + (ks*16 + (lane >> 4) * 8) * 2);
                ldmx4(a_hi[mt], base + off);
                if (NA == 2) ldmx4(a_lo[mt], base + DMAT + off);
            }
#pragma unroll
            for (int np = 0; np < 4; np++) {
                uint32_t off = (uint32_t)((wn*64 + np*16 + (lane & 7) + ((lane >> 4) & 1) * 8) * DPAD
                                          + (ks*16 + ((lane >> 3) & 1) * 8) * 2);
                uint32_t r[4];
                ldmx4(r, base + NA*DMAT + off);
                b_hi[np*2][0] = r[0]; b_hi[np*2][1] = r[1];
                b_hi[np*2+1][0] = r[2]; b_hi[np*2+1][1] = r[3];
                ldmx4(r, base + (NA+1)*DMAT + off);
                b_lo[np*2][0] = r[0]; b_lo[np*2][1] = r[1];
                b_lo[np*2+1][0] = r[2]; b_lo[np*2+1][1] = r[3];
            }
#pragma unroll
            for (int mt = 0; mt < 2; mt++)
#pragma unroll
                for (int nt = 0; nt < 8; nt++) {
                    mma16816(acc[mt][nt], a_hi[mt], b_hi[nt]);
                    mma16816(acc[mt][nt], a_hi[mt], b_lo[nt]);
                    if (NA == 2) mma16816(acc[mt][nt], a_lo[mt], b_hi[nt]);
                }
        }
        __syncthreads();
    }

#pragma unroll
    for (int mt = 0; mt < 2; mt++) {
        int r0 = m0 + wm*32 + mt*16 + (lane >> 2);
#pragma unroll
        for (int half = 0; half < 2; half++) {
            int row = r0 + half * 8;
#pragma unroll
            for (int nt = 0; nt < 8; nt++) {
                int col = n0 + wn*64 + nt*8 + (lane & 3) * 2;
                float v0 = acc[mt][nt][half*2+0], v1 = acc[mt][nt][half*2+1];
                if (bias) { v0 += bias[col]; v1 += bias[col+1]; }
                if (relu) { v0 = fmaxf(v0, 0.f); v1 = fmaxf(v1, 0.f); }
                if (Cf) {
                    float2 o; o.x = v0; o.y = v1;
                    *(float2*)(Cf + (size_t)row * N + col) = o;
                }
                if (Ch) {
                    f16 h0 = __float2half_rn(v0), h1 = __float2half_rn(v1);
                    *(f162*)(Ch + (size_t)row * N + col) = __halves2half2(h0, h1);
                    if (Cl) {
                        f16 l0 = __float2half_rn(v0 - __half2float(h0));
                        f16 l1 = __float2half_rn(v1 - __half2float(h1));
                        *(f162*)(Cl + (size_t)row * N + col) = __halves2half2(l0, l1);
                    }
                }
            }
        }
    }
}

// ---------------------------------------------------------------------------
// Fused scores + online softmax + P-split.
// CTA = 128 q-rows x full K=1024 keys for one (b,h). grid (Sq/128, B*H).
// Pass1: stream K tiles (3-buf cp.async), 3-product MMA, mask+scale,
//        write raw logits into attn (L2-resident scratch), online (m,s)/row.
// Pass2: reduce stats, reread logits (L2), write normalized attn + fp16 Ph.
// ---------------------------------------------------------------------------
#define SPAD 144
#define SMAT 18432                     // 128 rows x SPAD
#define FS_QOFF   0
#define FS_KOFF   (2*SMAT)             // 36864
#define FS_KSTAGE (2*SMAT)             // hi+lo per stage
#define FS_MASK   (FS_KOFF + 3*FS_KSTAGE)   // 147456
#define FS_STATS  (FS_MASK + 4096)          // 151552: float2 [2][128]
#define FS_FINAL  (FS_STATS + 2048)         // 153600: float2 [128]
#define FS_SMEM   (FS_FINAL + 1024)         // 154624

__global__ void __launch_bounds__(256, 1) scores_softmax_fused(
    const f16* __restrict__ Qh, const f16* __restrict__ Ql,
    const f16* __restrict__ KMh, const f16* __restrict__ KMl,
    const int* __restrict__ mask, float* __restrict__ attn,
    f16* __restrict__ Ph)
{
    extern __shared__ __align__(16) char dsm[];
    const uint32_t s0 = smem_u32(dsm);
    const int tid = threadIdx.x, lane = tid & 31, warp = tid >> 5;
    const int wm = warp & 3, wn = warp >> 2;
    const int bh = blockIdx.y, b = bh >> 4, h = bh & 15;
    const int q0 = blockIdx.x * 128;

    int*    mask_s  = (int*)   (dsm + FS_MASK);
    float2* stats   = (float2*)(dsm + FS_STATS);     // [wn][row]
    float2* finals  = (float2*)(dsm + FS_FINAL);     // [row]

    // mask into smem
#pragma unroll
    for (int i = 0; i < 4; i++) mask_s[tid + i * 256] = mask[b * Sq + tid + i * 256];

    // Q tile (hi+lo) + K stage 0 -> group 0; K stage 1 -> group 1
    {
        int r = tid >> 3, ch = tid & 7;
        const f16* qh = Qh + (size_t)(b * Sq + q0) * Dm + h * Dhd;
        const f16* ql = Ql + (size_t)(b * Sq + q0) * Dm + h * Dhd;
#pragma unroll
        for (int i = 0; i < 4; i++) {
            int rr = r + i * 32;
            CPA16(s0 + FS_QOFF + rr * SPAD + ch * 16,        qh + (size_t)rr * Dm + ch * 8);
            CPA16(s0 + FS_QOFF + SMAT + rr * SPAD + ch * 16, ql + (size_t)rr * Dm + ch * 8);
        }
    }
    auto load_k = [&](int st, int kt) {
        int r = tid >> 3, ch = tid & 7;
        uint32_t base = s0 + FS_KOFF + st * FS_KSTAGE;
        const f16* kh = KMh + (size_t)(b * Sq + kt * 128) * Dm + h * Dhd;
        const f16* kl = KMl + (size_t)(b * Sq + kt * 128) * Dm + h * Dhd;
#pragma unroll
        for (int i = 0; i < 4; i++) {
            int rr = r + i * 32;
            CPA16(base + rr * SPAD + ch * 16,        kh + (size_t)rr * Dm + ch * 8);
            CPA16(base + SMAT + rr * SPAD + ch * 16, kl + (size_t)rr * Dm + ch * 8);
        }
    };
    load_k(0, 0);
    CPA_COMMIT();                // group 0: Q + K0
    load_k(1, 1);
    CPA_COMMIT();                // group 1: K1

    // online stats per owned row: [mt][half]
    float rm[2][2], rs[2][2];
#pragma unroll
    for (int a = 0; a < 2; a++)
#pragma unroll
        for (int c = 0; c < 2; c++) { rm[a][c] = -INFINITY; rs[a][c] = 0.f; }

    for (int t = 0; t < 8; t++) {
        if (t + 2 < 8) { load_k((t + 2) % 3, t + 2); CPA_COMMIT(); }
        else           { CPA_COMMIT(); }
        CPA_WAIT2();
        __syncthreads();
        uint32_t kbase = s0 + FS_KOFF + (t % 3) * FS_KSTAGE;

        float acc[2][8][4];
#pragma unroll
        for (int a = 0; a < 2; a++)
#pragma unroll
            for (int bb = 0; bb < 8; bb++)
#pragma unroll
                for (int c = 0; c < 4; c++) acc[a][bb][c] = 0.f;

#pragma unroll
        for (int ks = 0; ks < 4; ks++) {
            uint32_t a_hi[2][4], a_lo[2][4], b_hi[8][2], b_lo[8][2];
#pragma unroll
            for (int mt = 0; mt < 2; mt++) {
                uint32_t off = (uint32_t)((wm*32 + mt*16 + (lane & 15)) * SPAD
                                          + (ks*16 + (lane >> 4) * 8) * 2);
                ldmx4(a_hi[mt], s0 + FS_QOFF + off);
                ldmx4(a_lo[mt], s0 + FS_QOFF + SMAT + off);
            }
#pragma unroll
            for (int np = 0; np < 4; np++) {
                uint32_t off = (uint32_t)((wn*64 + np*16 + (lane & 7) + ((lane >> 4) & 1) * 8) * SPAD
                                          + (ks*16 + ((lane >> 3) & 1) * 8) * 2);
                uint32_t r[4];
                ldmx4(r, kbase + off);
                b_hi[np*2][0] = r[0]; b_hi[np*2][1] = r[1];
                b_hi[np*2+1][0] = r[2]; b_hi[np*2+1][1] = r[3];
                ldmx4(r, kbase + SMAT + off);
                b_lo[np*2][0] = r[0]; b_lo[np*2][1] = r[1];
                b_lo[np*2+1][0] = r[2]; b_lo[np*2+1][1] = r[3];
            }
#pragma unroll
            for (int mt = 0; mt < 2; mt++)
#pragma unroll
                for (int nt = 0; nt < 8; nt++) {
                    mma16816(acc[mt][nt], a_hi[mt], b_hi[nt]);
                    mma16816(acc[mt][nt], a_hi[mt], b_lo[nt]);
                    mma16816(acc[mt][nt], a_lo[mt], b_hi[nt]);
                }
        }

        // epilogue: mask+scale, write raw logits, update online (m,s)
        const int n0 = t * 128;
#pragma unroll
        for (int mt = 0; mt < 2; mt++) {
#pragma unroll
            for (int half = 0; half < 2; half++) {
                int row = q0 + wm*32 + mt*16 + (lane >> 2) + half*8;
                float* ar = attn + ((size_t)bh * Sq + row) * Sq;
                float vals[16];
#pragma unroll
                for (int nt = 0; nt < 8; nt++) {
                    int col = n0 + wn*64 + nt*8 + (lane & 3) * 2;
                    float v0 = acc[mt][nt][half*2+0], v1 = acc[mt][nt][half*2+1];
                    v0 = mask_s[col]     ? -1.25e11f : v0 * 0.125f;
                    v1 = mask_s[col + 1] ? -1.25e11f : v1 * 0.125f;
                    float2 o; o.x = v0; o.y = v1;
                    *(float2*)(ar + col) = o;
                    vals[nt*2] = v0; vals[nt*2+1] = v1;
                }
                float tm = vals[0];
#pragma unroll
                for (int i = 1; i < 16; i++) tm = fmaxf(tm, vals[i]);
                float m_old = rm[mt][half];
                float m_new = fmaxf(m_old, tm);
                float s = rs[mt][half] * __expf(m_old - m_new);
#pragma unroll
                for (int i = 0; i < 16; i++) s += __expf(vals[i] - m_new);
                rm[mt][half] = m_new; rs[mt][half] = s;
            }
        }
        __syncthreads();
    }

    // reduce across the 4 lanes sharing each row (lane&3 differs)
#pragma unroll
    for (int mt = 0; mt < 2; mt++)
#pragma unroll
        for (int half = 0; half < 2; half++) {
            float m = rm[mt][half], s = rs[mt][half];
#pragma unroll
            for (int o = 1; o <= 2; o <<= 1) {
                float om = __shfl_xor_sync(0xffffffffu, m, o);
                float os = __shfl_xor_sync(0xffffffffu, s, o);
                float nm = fmaxf(m, om);
                s = s * __expf(m - nm) + os * __expf(om - nm);
                m = nm;
            }
            if ((lane & 3) == 0) {
                int row = wm*32 + mt*16 + (lane >> 2) + half*8;
                stats[wn * 128 + row] = make_float2(m, s);
            }
        }
    __syncthreads();

    // final per-row (max, 1/sum)
    if (tid < 128) {
        float2 p0 = stats[tid], p1 = stats[128 + tid];
        float M = fmaxf(p0.x, p1.x);
        float S = p0.y * __expf(p0.x - M) + p1.y * __expf(p1.x - M);
        finals[tid] = make_float2(M, 1.f / S);
    }
    __syncthreads();

    // pass2: normalize (coalesced; row i handled in iteration i)
    const size_t rbase = (size_t)bh * Sq + q0;
#pragma unroll 4
    for (int i = 0; i < 128; i++) {
        float2 fi = finals[i];
        float M = fi.x, inv = fi.y;
        size_t off = (rbase + i) * Sq + tid * 4;
        float4 v = *(float4*)(attn + off);
        v.x = __expf(v.x - M) * inv;
        v.y = __expf(v.y - M) * inv;
        v.z = __expf(v.z - M) * inv;
        v.w = __expf(v.w - M) * inv;
        *(float4*)(attn + off) = v;
        f162* H = (f162*)(Ph + off);
        H[0] = __floats2half2_rn(v.x, v.y);
        H[1] = __floats2half2_rn(v.z, v.w);
    }
}

// ---------------------------------------------------------------------------
// AV (mma.sync fp16, 2-product): per (b,h), 128q x 64d, K=1024, 3-stage pipe.
// ---------------------------------------------------------------------------
#define AVSTAGE 20480

__global__ void __launch_bounds__(256, 1) av_mma(
    const f16* __restrict__ Ph,
    const f16* __restrict__ Vth, const f16* __restrict__ Vtl,
    f16* __restrict__ avh)
{
    extern __shared__ __align__(16) char dsm[];
    const uint32_t s0 = smem_u32(dsm);
    const int tid = threadIdx.x, lane = tid & 31, warp = tid >> 5;
    const int wm = warp & 3, wn = warp >> 2;
    const int bh = blockIdx.y, b = bh >> 4, h = bh & 15;
    const int q0 = blockIdx.x * 128;
    const f16* pa = Ph + (size_t)bh * Sq * Sq + (size_t)q0 * Sq;
    const f16* pbh = Vth + (size_t)bh * 64 * Sq;
    const f16* pbl = Vtl + (size_t)bh * 64 * Sq;

    float acc[2][4][4];
#pragma unroll
    for (int a = 0; a < 2; a++)
#pragma unroll
        for (int bb = 0; bb < 4; bb++)
#pragma unroll
            for (int c = 0; c < 4; c++) acc[a][bb][c] = 0.f;

    auto load_stage = [&](int s, int k0) {
        uint32_t base = s0 + s * AVSTAGE;
        int row0 = tid >> 2, ch = tid & 3;
#pragma unroll
        for (int i = 0; i < 2; i++) {
            int row = row0 + i * 64;
            CPA16(base + row * DPAD + ch * 16, pa + (size_t)row * Sq + k0 + ch * 8);
        }
        CPA16(base + DMAT + row0 * DPAD + ch * 16,        pbh + (size_t)row0 * Sq + k0 + ch * 8);
        CPA16(base + DMAT + 5120 + row0 * DPAD + ch * 16, pbl + (size_t)row0 * Sq + k0 + ch * 8);
        CPA_COMMIT();
    };

    const int NS = Sq / 32;
    load_stage(0, 0);
    load_stage(1, 32);
    for (int s = 0; s < NS; s++) {
        if (s + 2 < NS) load_stage((s + 2) % 3, (s + 2) * 32);
        else            CPA_COMMIT();
        CPA_WAIT2();
        __syncthreads();
        uint32_t base = s0 + (s % 3) * AVSTAGE;
#pragma unroll
        for (int ks = 0; ks < 2; ks++) {
            uint32_t a_hi[2][4], b_hi[4][2], b_lo[4][2];
#pragma unroll
            for (int mt = 0; mt < 2; mt++) {
                uint32_t off = (uint32_t)((wm*32 + mt*16 + (lane & 15)) * DPAD
                                          + (ks*16 + (lane >> 4) * 8) * 2);
                ldmx4(a_hi[mt], base + off);
            }
#pragma unroll
            for (int np = 0; np < 2; np++) {
                uint32_t off = (uint32_t)((wn*32 + np*16 + (lane & 7) + ((lane >> 4) & 1) * 8) * DPAD
                                          + (ks*16 + ((lane >> 3) & 1) * 8) * 2);
                uint32_t r[4];
                ldmx4(r, base + DMAT + off);
                b_hi[np*2][0] = r[0]; b_hi[np*2][1] = r[1];
                b_hi[np*2+1][0] = r[2]; b_hi[np*2+1][1] = r[3];
                ldmx4(r, base + DMAT + 5120 + off);
                b_lo[np*2][0] = r[0]; b_lo[np*2][1] = r[1];
                b_lo[np*2+1][0] = r[2]; b_lo[np*2+1][1] = r[3];
            }
#pragma unroll
            for (int mt = 0; mt < 2; mt++)
#pragma unroll
                for (int nt = 0; nt < 4; nt++) {
                    mma16816(acc[mt][nt], a_hi[mt], b_hi[nt]);
                    mma16816(acc[mt][nt], a_hi[mt], b_lo[nt]);
                }
        }
        __syncthreads();
    }

#pragma unroll
    for (int mt = 0; mt < 2; mt++) {
        int r0 = q0 + wm*32 + mt*16 + (lane >> 2);
#pragma unroll
        for (int half = 0; half < 2; half++) {
            int row = r0 + half * 8;
            f16* orow = avh + (size_t)(b * Sq + row) * Dm + h * Dhd;
#pragma unroll
            for (int nt = 0; nt < 4; nt++) {
                int col = wn*32 + nt*8 + (lane & 3) * 2;
                *(f162*)(orow + col) = __floats2half2_rn(acc[mt][nt][half*2+0],
                                                         acc[mt][nt][half*2+1]);
            }
        }
    }
}

// ---------------------------------------------------------------------------
// LayerNorm(a + r), torch semantics (ddof=1, eps on std); optional fp16 hi out.
// ---------------------------------------------------------------------------
__global__ void __launch_bounds__(256) ln_kernel(
    const float* __restrict__ a, const float* __restrict__ r,
    const float* __restrict__ gamma, const float* __restrict__ beta,
    float* __restrict__ y, f16* __restrict__ yh)
{
    __shared__ float sh[32];
    const int row = blockIdx.x;
    const int tid = threadIdx.x;

    float4 v = reinterpret_cast<const float4*>(a + (size_t)row * Dm)[tid];
    float4 vr = reinterpret_cast<const float4*>(r + (size_t)row * Dm)[tid];
    v.x += vr.x; v.y += vr.y; v.z += vr.z; v.w += vr.w;

    float s = v.x + v.y + v.z + v.w;
#pragma unroll
    for (int o = 16; o; o >>= 1) s += __shfl_xor_sync(0xffffffffu, s, o);
    if ((tid & 31) == 0) sh[tid >> 5] = s;
    __syncthreads();
    if (tid < 32) {
        float m = (tid < 8) ? sh[tid] : 0.f;
#pragma unroll
        for (int o = 4; o; o >>= 1) m += __shfl_xor_sync(0xffffffffu, m, o);
        if (tid == 0) sh[0] = m;
    }
    __syncthreads();
    float mean = sh[0] * (1.0f / Dm);
    __syncthreads();

    float dx = v.x - mean, dy = v.y - mean, dz = v.z - mean, dw = v.w - mean;
    float s2 = dx*dx + dy*dy + dz*dz + dw*dw;
#pragma unroll
    for (int o = 16; o; o >>= 1) s2 += __shfl_xor_sync(0xffffffffu, s2, o);
    if ((tid & 31) == 0) sh[tid >> 5] = s2;
    __syncthreads();
    if (tid < 32) {
        float m = (tid < 8) ? sh[tid] : 0.f;
#pragma unroll
        for (int o = 4; o; o >>= 1) m += __shfl_xor_sync(0xffffffffu, m, o);
        if (tid == 0) sh[0] = m;
    }
    __syncthreads();
    float var = sh[0] * (1.0f / (Dm - 1));
    float inv = 1.0f / (sqrtf(var) + 1e-8f);

    float4 g = reinterpret_cast<const float4*>(gamma)[tid];
    float4 bb = reinterpret_cast<const float4*>(beta)[tid];
    float4 o;
    o.x = g.x * dx * inv + bb.x;
    o.y = g.y * dy * inv + bb.y;
    o.z = g.z * dz * inv + bb.z;
    o.w = g.w * dw * inv + bb.w;
    reinterpret_cast<float4*>(y + (size_t)row * Dm)[tid] = o;

    if (yh) {
        f162* H = reinterpret_cast<f162*>(yh + (size_t)row * Dm);
        H[2*tid]   = __floats2half2_rn(o.x, o.y);
        H[2*tid+1] = __floats2half2_rn(o.z, o.w);
    }
}

// ---------------------------------------------------------------------------
// Launch
// ---------------------------------------------------------------------------
extern "C" void kernel_launch(void* const* d_in, const int* in_sizes, int n_in,
                              void* d_out, int out_size)
{
    const float* x      = (const float*)d_in[0];
    const int*   mask   = (const int*)  d_in[1];
    const float* W[6]   = { (const float*)d_in[2], (const float*)d_in[3],
                            (const float*)d_in[4], (const float*)d_in[5],
                            (const float*)d_in[6], (const float*)d_in[8] };
    const float* b1     = (const float*)d_in[7];
    const float* b2     = (const float*)d_in[9];
    const float* gamma1 = (const float*)d_in[10];
    const float* beta1  = (const float*)d_in[11];
    const float* gamma2 = (const float*)d_in[12];
    const float* beta2  = (const float*)d_in[13];
    float* out = (float*)d_out;

    float *pV,*px1,*pff,*pattn_fb;
    cudaGetSymbolAddress((void**)&pV, g_V);
    cudaGetSymbolAddress((void**)&px1, g_x1);
    cudaGetSymbolAddress((void**)&pff, g_ff);
    cudaGetSymbolAddress((void**)&pattn_fb, g_attn_fb);
    f16 *pxh,*pxl,*pQh,*pQl,*pKh,*pKl,*pavh,*px1h,*ph1h,*pWh,*pWl,*pVth,*pVtl,*pPh;
    cudaGetSymbolAddress((void**)&pxh, g_xh);   cudaGetSymbolAddress((void**)&pxl, g_xl);
    cudaGetSymbolAddress((void**)&pQh, g_Qh);   cudaGetSymbolAddress((void**)&pQl, g_Ql);
    cudaGetSymbolAddress((void**)&pKh, g_Kh);   cudaGetSymbolAddress((void**)&pKl, g_Kl);
    cudaGetSymbolAddress((void**)&pavh, g_avh);
    cudaGetSymbolAddress((void**)&px1h, g_x1h);
    cudaGetSymbolAddress((void**)&ph1h, g_h1h);
    cudaGetSymbolAddress((void**)&pWh, g_Wh);   cudaGetSymbolAddress((void**)&pWl, g_Wl);
    cudaGetSymbolAddress((void**)&pVth, g_Vth); cudaGetSymbolAddress((void**)&pVtl, g_Vtl);
    cudaGetSymbolAddress((void**)&pPh, g_Ph);

    float* attn = ((size_t)out_size >= OUT_ELEMS + ATTN_ELEMS) ? (out + OUT_ELEMS) : pattn_fb;

    const int GM2_SMEM = 3 * 4 * DMAT;     // 122880
    const int GM1_SMEM = 3 * 3 * DMAT;     // 92160
    const int AV_SMEM  = 3 * AVSTAGE;      // 61440
    cudaFuncSetAttribute(gemm_mma<2>, cudaFuncAttributeMaxDynamicSharedMemorySize, GM2_SMEM);
    cudaFuncSetAttribute(gemm_mma<1>, cudaFuncAttributeMaxDynamicSharedMemorySize, GM1_SMEM);
    cudaFuncSetAttribute(scores_softmax_fused, cudaFuncAttributeMaxDynamicSharedMemorySize, FS_SMEM);
    cudaFuncSetAttribute(av_mma,      cudaFuncAttributeMaxDynamicSharedMemorySize, AV_SMEM);

    dim3 blk(256);
    const int N4x = (Mrows * Dm) / 4;
    const int N4w = (Dm * Dm) / 4;
    dim3 gGemm(Dm / 128, Mrows / 128);     // (8, 16)
    const size_t WS = (size_t)Dm * Dm;

    // Splits: x + 6 weights (hi/lo)
    split_kernel<<<N4x / 256, blk>>>(x, pxh, pxl, N4x);
    for (int w = 0; w < 6; w++)
        split_kernel<<<N4w / 256, blk>>>(W[w], pWh + w * WS, pWl + w * WS, N4w);

    // QKV projections (3-product). Q,K -> fp16 hi/lo; V -> fp32.
    gemm_mma<2><<<gGemm, blk, GM2_SMEM>>>(pxh, pxl, pWh + 0*WS, pWl + 0*WS,
        nullptr, 0, nullptr, pQh, pQl, Mrows, Dm, Dm);
    gemm_mma<2><<<gGemm, blk, GM2_SMEM>>>(pxh, pxl, pWh + 1*WS, pWl + 1*WS,
        nullptr, 0, nullptr, pKh, pKl, Mrows, Dm, Dm);
    gemm_mma<2><<<gGemm, blk, GM2_SMEM>>>(pxh, pxl, pWh + 2*WS, pWl + 2*WS,
        nullptr, 0, pV, nullptr, nullptr, Mrows, Dm, Dm);

    vtrans_kernel<<<dim3(Sq / 128, 32), blk>>>(pV, pVth, pVtl);

    // Fused scores + softmax + P-split -> attn (fp32) + Ph (fp16)
    scores_softmax_fused<<<dim3(Sq / 128, Bsz * Hn), blk, FS_SMEM>>>(
        pQh, pQl, pKh, pKl, mask, attn, pPh);

    // attn @ V (2-product) -> avh fp16
    av_mma<<<dim3(Sq / 128, Bsz * Hn), blk, AV_SMEM>>>(pPh, pVth, pVtl, pavh);

    // Output projection (2-product) -> fp32, then LN1 (+x1h fp16)
    gemm_mma<1><<<gGemm, blk, GM1_SMEM>>>(pavh, nullptr, pWh + 3*WS, pWl + 3*WS,
        nullptr, 0, pff, nullptr, nullptr, Mrows, Dm, Dm);
    ln_kernel<<<Mrows, blk>>>(x, pff, gamma1, beta1, px1, px1h);

    // FFN: W1 (bias+relu) -> h1h fp16 only; W2 (bias) -> fp32 ff
    gemm_mma<1><<<gGemm, blk, GM1_SMEM>>>(px1h, nullptr, pWh + 4*WS, pWl + 4*WS,
        b1, 1, nullptr, ph1h, nullptr, Mrows, Dm, Dm);
    gemm_mma<1><<<gGemm, blk, GM1_SMEM>>>(ph1h, nullptr, pWh + 5*WS, pWl + 5*WS,
        b2, 0, pff, nullptr, nullptr, Mrows, Dm, Dm);

    // LN2 -> out
    ln_kernel<<<Mrows, blk>>>(px1, pff, gamma2, beta2, out, nullptr);
}